// round 16
// baseline (speedup 1.0000x reference)
#include <cuda_runtime.h>
#include <cstdint>

#define BB 4
#define SQ 4
#define HH 32
#define HKV 8
#define GG 4
#define DD 128
#define DVV 128
#define SMAX 8192
#define RR 16
#define TT 32
#define NSPLIT 32
#define NTHREADS 128
#define SCALE 0.08838834764831845f
#define M0 8.0f

// smem (bytes): Q 8K | K 2x16K | V 2x16K | P 4x512
#define SMEM_Q 0
#define SMEM_K 8192
#define SMEM_V (8192 + 32768)
#define SMEM_P (8192 + 65536)
#define SMEM_BYTES (SMEM_P + 2048)   // 75776 x3 <= 228KB (occ 3)

typedef unsigned long long u64;

__device__ __forceinline__ void fma2(u64& d, u64 a, u64 b) {
    asm("fma.rn.f32x2 %0, %1, %2, %0;" : "+l"(d) : "l"(a), "l"(b));
}
__device__ __forceinline__ u64 pack2(float x) {
    u64 r; asm("mov.b64 %0, {%1, %1};" : "=l"(r) : "f"(x)); return r;
}
__device__ __forceinline__ float2 unpack2(u64 a) {
    float2 f; asm("mov.b64 {%0, %1}, %2;" : "=f"(f.x), "=f"(f.y) : "l"(a)); return f;
}

// split-K partial scratch (static device memory; no allocation)
__device__ float g_po[(size_t)BB * HKV * NSPLIT * RR * DVV];
__device__ float g_pl[BB * HKV * NSPLIT * RR];

extern "C" __global__ void __launch_bounds__(NTHREADS, 3)
attn_split_kernel(const float* __restrict__ Q, const float* __restrict__ K,
                  const float* __restrict__ V, const int* __restrict__ seqlens)
{
    extern __shared__ char smem[];
    float4* qs4 = (float4*)(smem + SMEM_Q);
    float4* ks4 = (float4*)(smem + SMEM_K);
    float4* vs4 = (float4*)(smem + SMEM_V);

    const int split = blockIdx.x;
    const int hkv   = blockIdx.y;
    const int b     = blockIdx.z;
    const int tid   = threadIdx.x;
    const int lane  = tid & 31;
    const int wid   = tid >> 5;

    const int L = seqlens[b];
    const int chunk = (L + NSPLIT - 1) / NSPLIT;
    const int c0    = split * chunk;
    int n_eff = L - c0;
    if (n_eff > chunk) n_eff = chunk;
    const int part = (b * HKV + hkv) * NSPLIT + split;
    const int hi   = c0 + n_eff - 1;

    // quadrant ownership: warp = (row-half rh, token-half th)
    const int rh = wid & 1;
    const int th = wid >> 1;
    const int barid = th + 1;            // pair barrier id (1 or 2)
    // lane tiling: tp = token-pair 0..7, rq = row-pair 0..3
    const int tp = lane >> 2;
    const int rq = lane & 3;
    const int r0  = rh * 8 + 2 * rq;     // global rows (0..15)
    const int r1  = r0 + 1;
    const int tl0 = th * 16 + 2 * tp;    // tile-local tokens (0..31)
    const int tl1 = tl0 + 1;
    int lim0 = L - SQ + (r0 & 3); if (lim0 > hi) lim0 = hi;
    int lim1 = L - SQ + (r1 & 3); if (lim1 > hi) lim1 = hi;

    float* sPw = (float*)(smem + SMEM_P) + wid * 128;   // [16 tok][8 rows]

    // O: 8 rows x 4 dims (lane*4..+3) as u64 pairs
    u64 o[16];
#pragma unroll
    for (int i = 0; i < 16; i++) o[i] = 0ull;
    float lp0 = 0.f, lp1 = 0.f;   // l partials for rows r0,r1 over own tokens

    const int ntiles = (n_eff + TT - 1) / TT;
    const size_t kvbase = ((size_t)b * SMAX * HKV + hkv) * DD;

    // warp loads its pair's half-slice: rh==0 -> K half, rh==1 -> V half
    auto issue = [&](int it) {
        const int tb   = c0 + it * TT + th * 16;
        const int bufo = (it & 1) * (TT * 32);
#pragma unroll
        for (int j = 0; j < 16; j++) {
            int ti = tb + j;
            if (ti > SMAX - 1) ti = SMAX - 1;      // clamp (masked anyway)
            const int tl = th * 16 + j;
            if (rh == 0) {
                const float* gk = K + kvbase + (size_t)ti * (HKV * DD) + lane * 4;
                unsigned ka = (unsigned)__cvta_generic_to_shared(
                    &ks4[bufo + tl * 32 + (lane ^ tl)]);
                asm volatile("cp.async.cg.shared.global [%0], [%1], 16;\n" :: "r"(ka), "l"(gk));
            } else {
                const float* gv = V + kvbase + (size_t)ti * (HKV * DD) + lane * 4;
                unsigned va = (unsigned)__cvta_generic_to_shared(
                    &vs4[bufo + tl * 32 + lane]);
                asm volatile("cp.async.cg.shared.global [%0], [%1], 16;\n" :: "r"(va), "l"(gv));
            }
        }
        asm volatile("cp.async.commit_group;\n" ::: "memory");
    };

    issue(0);
    issue(1);

    // ---- Q (pre-scaled) into smem, additive row swizzle (d4 + 4r) ----
#pragma unroll
    for (int i = 0; i < 4; i++) {
        int f  = i * NTHREADS + tid;
        int r  = f >> 5;
        int d4 = f & 31;
        int h  = hkv * GG + (r >> 2);
        int mm = r & 3;
        const float4 qv = *(const float4*)(Q + ((size_t)((b * SQ + mm) * HH + h)) * DD + d4 * 4);
        float4 qq;
        qq.x = qv.x * SCALE; qq.y = qv.y * SCALE;
        qq.z = qv.z * SCALE; qq.w = qv.w * SCALE;
        qs4[r * 32 + ((d4 + 4 * r) & 31)] = qq;
    }
    __syncthreads();   // Q visible (once)

    const int sw0 = 4 * r0;   // Q swizzle offsets (mod 32 applied per-iter)
    const int sw1 = 4 * r1;

    for (int it = 0; it < ntiles; ++it) {
        asm volatile("cp.async.wait_group 1;\n" ::: "memory");   // own slice of tile it
        asm volatile("bar.sync %0, 64;\n" :: "r"(barid) : "memory");  // pair: K+V half ready

        const int jb   = c0 + it * TT;
        const int bufo = (it & 1) * (TT * 32);

        // ---- S: rows {r0,r1} x tokens {tl0,tl1}, full D, fp32 packed pairs ----
        u64 a00 = 0ull, a01 = 0ull, a10 = 0ull, a11 = 0ull;
        {
            const ulonglong2* kb = (const ulonglong2*)(ks4 + bufo);
            const ulonglong2* qb = (const ulonglong2*)qs4;
            const int k0r = tl0 * 32, k1r = tl1 * 32;
#pragma unroll
            for (int d4 = 0; d4 < 32; d4++) {
                ulonglong2 k0 = kb[k0r + (d4 ^ tl0)];
                ulonglong2 k1 = kb[k1r + (d4 ^ tl1)];
                ulonglong2 q0 = qb[r0 * 32 + ((d4 + sw0) & 31)];
                ulonglong2 q1 = qb[r1 * 32 + ((d4 + sw1) & 31)];
                fma2(a00, q0.x, k0.x); fma2(a00, q0.y, k0.y);
                fma2(a01, q0.x, k1.x); fma2(a01, q0.y, k1.y);
                fma2(a10, q1.x, k0.x); fma2(a10, q1.y, k0.y);
                fma2(a11, q1.x, k1.x); fma2(a11, q1.y, k1.y);
            }
        }

        // ---- fixed-base softmax (no cross-lane combine) + warp-private P ----
        {
            const int gt0 = jb + tl0;
            const int gt1 = jb + tl1;
            float2 f00 = unpack2(a00), f01 = unpack2(a01);
            float2 f10 = unpack2(a10), f11 = unpack2(a11);
            float s00 = f00.x + f00.y, s01 = f01.x + f01.y;
            float s10 = f10.x + f10.y, s11 = f11.x + f11.y;
            float p00 = (gt0 <= lim0) ? __expf(s00 - M0) : 0.f;   // (t0,r0)
            float p01 = (gt1 <= lim0) ? __expf(s01 - M0) : 0.f;   // (t1,r0)
            float p10 = (gt0 <= lim1) ? __expf(s10 - M0) : 0.f;   // (t0,r1)
            float p11 = (gt1 <= lim1) ? __expf(s11 - M0) : 0.f;   // (t1,r1)
            lp0 += p00 + p01;
            lp1 += p10 + p11;
            // P[tloc][rowlocal]: rows 2rq,2rq+1 as float2
            *(float2*)(sPw + (2 * tp)     * 8 + 2 * rq) = make_float2(p00, p10);
            *(float2*)(sPw + (2 * tp + 1) * 8 + 2 * rq) = make_float2(p01, p11);
        }
        __syncwarp();

        // ---- O(8 rows) += P V over own 16 tokens; lane owns dims lane*4..+3 ----
        {
            const ulonglong2* vb = (const ulonglong2*)(vs4 + bufo);
#pragma unroll
            for (int t = 0; t < 16; t++) {
                const int tl = th * 16 + t;
                ulonglong2 vv = vb[tl * 32 + lane];
                float4 pA = *(const float4*)(sPw + t * 8);       // rows 0..3 (local)
                float4 pB = *(const float4*)(sPw + t * 8 + 4);   // rows 4..7
                u64 q;
                q = pack2(pA.x); fma2(o[0],  q, vv.x); fma2(o[1],  q, vv.y);
                q = pack2(pA.y); fma2(o[2],  q, vv.x); fma2(o[3],  q, vv.y);
                q = pack2(pA.z); fma2(o[4],  q, vv.x); fma2(o[5],  q, vv.y);
                q = pack2(pA.w); fma2(o[6],  q, vv.x); fma2(o[7],  q, vv.y);
                q = pack2(pB.x); fma2(o[8],  q, vv.x); fma2(o[9],  q, vv.y);
                q = pack2(pB.y); fma2(o[10], q, vv.x); fma2(o[11], q, vv.y);
                q = pack2(pB.z); fma2(o[12], q, vv.x); fma2(o[13], q, vv.y);
                q = pack2(pB.w); fma2(o[14], q, vv.x); fma2(o[15], q, vv.y);
            }
        }
        asm volatile("bar.sync %0, 64;\n" :: "r"(barid) : "memory");  // pair done w/ buffer
        issue(it + 2);
    }

    asm volatile("cp.async.wait_group 0;\n" ::: "memory");   // drain own prefetches

    // ---- l: reduce over tp (lane bits 2..4) ----
    lp0 += __shfl_xor_sync(0xffffffffu, lp0, 4);
    lp0 += __shfl_xor_sync(0xffffffffu, lp0, 8);
    lp0 += __shfl_xor_sync(0xffffffffu, lp0, 16);
    lp1 += __shfl_xor_sync(0xffffffffu, lp1, 4);
    lp1 += __shfl_xor_sync(0xffffffffu, lp1, 8);
    lp1 += __shfl_xor_sync(0xffffffffu, lp1, 16);

    __syncthreads();   // all warps done; K/V/P smem dead

    // ---- merge token-halves: dump O into dead K region ----
    float* om = (float*)(smem + SMEM_K) + wid * 1024;   // [8 rows][128]
#pragma unroll
    for (int r = 0; r < 8; r++) {
        float2 x = unpack2(o[2 * r]);
        float2 y = unpack2(o[2 * r + 1]);
        *(float4*)(om + r * 128 + lane * 4) = make_float4(x.x, x.y, y.x, y.y);
    }
    float* sLm = (float*)(smem + SMEM_V);   // [4 wid][8 rows]
    if (lane < 4) {
        sLm[wid * 8 + 2 * lane]     = lp0;
        sLm[wid * 8 + 2 * lane + 1] = lp1;
    }
    __syncthreads();

    // ---- final: row r = th0-warp + th1-warp of its row-half ----
    {
        const int pr = tid >> 3;            // row 0..15
        const int k8 = tid & 7;             // dim octet (16 floats)
        const int w0 = pr >> 3;             // rh -> wid of th0 warp
        const int lr = pr & 7;
        const float* m0 = (float*)(smem + SMEM_K) + w0 * 1024 + lr * 128 + k8 * 16;
        const float* m1 = m0 + 2048;        // wid w0+2 (th1)
        float* po = g_po + ((size_t)part * RR + pr) * DVV + k8 * 16;
#pragma unroll
        for (int j = 0; j < 4; j++) {
            float4 s0 = *(const float4*)(m0 + j * 4);
            float4 s1 = *(const float4*)(m1 + j * 4);
            *(float4*)(po + j * 4) = make_float4(s0.x + s1.x, s0.y + s1.y,
                                                 s0.z + s1.z, s0.w + s1.w);
        }
        if (tid < RR) {
            const int rr = tid;
            g_pl[part * RR + rr] = sLm[(rr >> 3) * 8 + (rr & 7)]
                                 + sLm[((rr >> 3) + 2) * 8 + (rr & 7)];
        }
    }
}

extern "C" __global__ void __launch_bounds__(128)
attn_reduce_kernel(float* __restrict__ out)
{
    __shared__ float4 sV[4][32];
    __shared__ float  sL[4];

    const int hkv = blockIdx.x;
    const int b   = blockIdx.y;
    const int r   = blockIdx.z;          // 0..15
    const int tid = threadIdx.x;
    const int sg  = tid >> 5;            // split group 0..3 (8 splits each)
    const int d4  = tid & 31;
    const int pb  = (b * HKV + hkv) * NSPLIT;

    const float4* po4 = (const float4*)g_po;

    float lt = 0.f;
    float4 acc = make_float4(0.f, 0.f, 0.f, 0.f);
#pragma unroll
    for (int s = 0; s < 8; s++) {
        const int ss = pb + sg * 8 + s;
        lt += g_pl[ss * RR + r];
        float4 x = po4[((size_t)ss * RR + r) * 32 + d4];
        acc.x += x.x; acc.y += x.y; acc.z += x.z; acc.w += x.w;
    }
    sV[sg][d4] = acc;
    if (d4 == 0) sL[sg] = lt;
    __syncthreads();

    if (sg == 0) {
        float4 a0 = sV[0][d4], a1 = sV[1][d4], a2 = sV[2][d4], a3 = sV[3][d4];
        float inv = 1.f / (sL[0] + sL[1] + sL[2] + sL[3]);
        float4 rslt = make_float4((a0.x + a1.x + a2.x + a3.x) * inv,
                                  (a0.y + a1.y + a2.y + a3.y) * inv,
                                  (a0.z + a1.z + a2.z + a3.z) * inv,
                                  (a0.w + a1.w + a2.w + a3.w) * inv);
        const int mq = r & 3;
        const int gi = r >> 2;
        *(float4*)(out + ((size_t)((b * SQ + mq) * HH + hkv * GG + gi)) * DVV + d4 * 4) = rslt;
    }
}

extern "C" void kernel_launch(void* const* d_in, const int* in_sizes, int n_in,
                              void* d_out, int out_size)
{
    const float* Q  = (const float*)d_in[0];
    const float* K  = (const float*)d_in[1];
    const float* V  = (const float*)d_in[2];
    const int*   sl = (const int*)d_in[3];

    cudaFuncSetAttribute(attn_split_kernel,
                         cudaFuncAttributeMaxDynamicSharedMemorySize, SMEM_BYTES);

    attn_split_kernel<<<dim3(NSPLIT, HKV, BB), NTHREADS, SMEM_BYTES>>>(Q, K, V, sl);
    attn_reduce_kernel<<<dim3(HKV, BB, RR), 128>>>((float*)d_out);
}

// round 17
// speedup vs baseline: 2.6235x; 2.6235x over previous
#include <cuda_runtime.h>
#include <cstdint>

#define BB 4
#define SQ 4
#define HH 32
#define HKV 8
#define GG 4
#define DD 128
#define DVV 128
#define SMAX 8192
#define RR 16
#define TT 32
#define NSPLIT 32
#define CHUNK (SMAX / NSPLIT)
#define NTHREADS 128
#define SCALE 0.08838834764831845f

// smem layout (bytes)
#define SMEM_Q_OFF 0
#define SMEM_K_OFF 8192
#define SMEM_V_OFF (8192 + 32768)
#define SMEM_P_OFF (8192 + 32768 + 32768)   // [4 warps][32 tok][4 rows] float = 2048
#define SMEM_BYTES (SMEM_P_OFF + 2048)

typedef unsigned long long u64;

__device__ __forceinline__ void fma2(u64& d, u64 a, u64 b) {
    asm("fma.rn.f32x2 %0, %1, %2, %0;" : "+l"(d) : "l"(a), "l"(b));
}
__device__ __forceinline__ void mul2(u64& d, u64 a) {
    asm("mul.rn.f32x2 %0, %0, %1;" : "+l"(d) : "l"(a));
}
__device__ __forceinline__ u64 pack2(float x) {
    u64 r; asm("mov.b64 %0, {%1, %1};" : "=l"(r) : "f"(x)); return r;
}
__device__ __forceinline__ float2 unpack2(u64 a) {
    float2 f; asm("mov.b64 {%0, %1}, %2;" : "=f"(f.x), "=f"(f.y) : "l"(a)); return f;
}

// split-K partial scratch (static device memory; no allocation)
__device__ float g_po[(size_t)BB * HKV * NSPLIT * RR * DVV];
__device__ float g_pm[BB * HKV * NSPLIT * RR];
__device__ float g_pl[BB * HKV * NSPLIT * RR];

extern "C" __global__ void __launch_bounds__(NTHREADS, 3)
attn_split_kernel(const float* __restrict__ Q, const float* __restrict__ K,
                  const float* __restrict__ V, const int* __restrict__ seqlens)
{
    extern __shared__ char smem[];
    float4* qs4 = (float4*)(smem + SMEM_Q_OFF);
    float4* ks4 = (float4*)(smem + SMEM_K_OFF);
    float4* vs4 = (float4*)(smem + SMEM_V_OFF);
    float*  sP  = (float*)(smem + SMEM_P_OFF);   // [wid][tok][4 rows]

    const int split = blockIdx.x;
    const int hkv   = blockIdx.y;
    const int b     = blockIdx.z;
    const int tid   = threadIdx.x;
    const int lane  = tid & 31;
    const int wid   = tid >> 5;

    const int L  = seqlens[b];
    const int c0 = split * CHUNK;
    int n_eff = L - c0;
    if (n_eff > CHUNK) n_eff = CHUNK;
    const int part = (b * HKV + hkv) * NSPLIT + split;

    // warp owns rows R..R+3 for the WHOLE pipeline (QK, softmax, PV)
    const int R = wid * 4;
    float* sPw = sP + wid * (TT * 4);

    // QK lane mapping: tp = token-pair, dh = dim-half
    const int tp = lane & 15;
    const int dh = lane >> 4;
    const int t0 = 2 * tp;

    float m[4], l[4];
#pragma unroll
    for (int i = 0; i < 4; i++) { m[i] = -1e30f; l[i] = 0.f; }
    // PV accumulators: 4 rows x 4 dims (dims lane*4 .. lane*4+3)
    u64 o[8];
#pragma unroll
    for (int i = 0; i < 8; i++) o[i] = 0ull;

    if (n_eff > 0) {
        // ---- Q (pre-scaled) into smem ----
#pragma unroll
        for (int i = 0; i < 4; i++) {
            int f  = i * NTHREADS + tid;
            int r  = f >> 5;
            int d4 = f & 31;
            int h  = hkv * GG + (r >> 2);
            int mm = r & 3;
            const float4 qv = *(const float4*)(Q + ((size_t)((b * SQ + mm) * HH + h)) * DD + d4 * 4);
            float4 qq;
            qq.x = qv.x * SCALE; qq.y = qv.y * SCALE;
            qq.z = qv.z * SCALE; qq.w = qv.w * SCALE;
            qs4[f] = qq;
        }

        const int ntiles = (n_eff + TT - 1) / TT;
        const size_t kvbase = ((size_t)b * SMAX * HKV + hkv) * DD;

        auto issue_tile = [&](int it) {
            const int jb   = c0 + it * TT;
            const int bufo = (it & 1) * (TT * 32);
#pragma unroll
            for (int i = 0; i < 8; i++) {
                int f  = i * NTHREADS + tid;   // 0..1023
                int t  = f >> 5;
                int d4 = f & 31;
                const float* gk = K + kvbase + (size_t)(jb + t) * (HKV * DD) + d4 * 4;
                const float* gv = V + kvbase + (size_t)(jb + t) * (HKV * DD) + d4 * 4;
                unsigned ka = (unsigned)__cvta_generic_to_shared(&ks4[bufo + t * 32 + (d4 ^ (t >> 1))]);
                unsigned va = (unsigned)__cvta_generic_to_shared(&vs4[bufo + t * 32 + d4]);
                asm volatile("cp.async.cg.shared.global [%0], [%1], 16;\n" :: "r"(ka), "l"(gk));
                asm volatile("cp.async.cg.shared.global [%0], [%1], 16;\n" :: "r"(va), "l"(gv));
            }
            asm volatile("cp.async.commit_group;\n" ::: "memory");
        };

        issue_tile(0);
        if (ntiles > 1) issue_tile(1);

        for (int it = 0; it < ntiles; ++it) {
            if (it < ntiles - 1) asm volatile("cp.async.wait_group 1;\n" ::: "memory");
            else                 asm volatile("cp.async.wait_group 0;\n" ::: "memory");
            __syncthreads();   // A: tile (and Q on it==0) visible

            const int jb   = c0 + it * TT;
            const int bufo = (it & 1) * (TT * 32);

            // ---- S = Q K^T : 4 rows x 2 tokens x d-half per thread ----
            u64 acc[4][2];
#pragma unroll
            for (int rr = 0; rr < 4; rr++) { acc[rr][0] = 0ull; acc[rr][1] = 0ull; }
            {
                const ulonglong2* kb = (const ulonglong2*)(ks4 + bufo);
                const ulonglong2* qb = (const ulonglong2*)qs4;
#pragma unroll
                for (int i = 0; i < 16; i++) {
                    const int d4  = dh * 16 + i;
                    const int col = d4 ^ tp;
                    ulonglong2 k0 = kb[t0 * 32 + col];
                    ulonglong2 k1 = kb[(t0 + 1) * 32 + col];
#pragma unroll
                    for (int rr = 0; rr < 4; rr++) {
                        ulonglong2 q = qb[(R + rr) * 32 + d4];
                        fma2(acc[rr][0], q.x, k0.x);
                        fma2(acc[rr][0], q.y, k0.y);
                        fma2(acc[rr][1], q.x, k1.x);
                        fma2(acc[rr][1], q.y, k1.y);
                    }
                }
            }

            // ---- in-warp online softmax for rows R..R+3 ----
            float p[4][2];
            {
                float s[4][2];
#pragma unroll
                for (int rr = 0; rr < 4; rr++) {
#pragma unroll
                    for (int j = 0; j < 2; j++) {
                        float2 f = unpack2(acc[rr][j]);
                        float v  = f.x + f.y;
                        v += __shfl_xor_sync(0xffffffffu, v, 16);  // combine d-halves
                        s[rr][j] = v;
                    }
                }
                float mx[4];
#pragma unroll
                for (int rr = 0; rr < 4; rr++) {
                    const int lim = L - SQ + ((R + rr) & 3);
                    if (jb + t0     > lim) s[rr][0] = -1e30f;
                    if (jb + t0 + 1 > lim) s[rr][1] = -1e30f;
                    mx[rr] = fmaxf(s[rr][0], s[rr][1]);
                }
#pragma unroll
                for (int off = 8; off >= 1; off >>= 1) {
#pragma unroll
                    for (int rr = 0; rr < 4; rr++)
                        mx[rr] = fmaxf(mx[rr], __shfl_xor_sync(0xffffffffu, mx[rr], off));
                }
                float corr[4], sum[4];
#pragma unroll
                for (int rr = 0; rr < 4; rr++) {
                    float nm = fmaxf(m[rr], mx[rr]);
                    p[rr][0] = (s[rr][0] > -1e29f) ? __expf(s[rr][0] - nm) : 0.f;
                    p[rr][1] = (s[rr][1] > -1e29f) ? __expf(s[rr][1] - nm) : 0.f;
                    corr[rr] = __expf(m[rr] - nm);
                    m[rr]    = nm;
                    sum[rr]  = p[rr][0] + p[rr][1];
                }
#pragma unroll
                for (int off = 8; off >= 1; off >>= 1) {
#pragma unroll
                    for (int rr = 0; rr < 4; rr++)
                        sum[rr] += __shfl_xor_sync(0xffffffffu, sum[rr], off);
                }
#pragma unroll
                for (int rr = 0; rr < 4; rr++)
                    l[rr] = l[rr] * corr[rr] + sum[rr];

                // stage P (warp-private): [tok][4 rows]
                if (dh == 0) {
                    *(float4*)(sPw + t0 * 4)       = make_float4(p[0][0], p[1][0], p[2][0], p[3][0]);
                    *(float4*)(sPw + (t0 + 1) * 4) = make_float4(p[0][1], p[1][1], p[2][1], p[3][1]);
                }
                __syncwarp();

                // rescale accumulators
#pragma unroll
                for (int rr = 0; rr < 4; rr++) {
                    u64 cc = pack2(corr[rr]);
                    mul2(o[2 * rr],     cc);
                    mul2(o[2 * rr + 1], cc);
                }
            }

            // ---- O(rows R..R+3) += P V : lane owns dims lane*4..+3 ----
            {
                const ulonglong2* vb = (const ulonglong2*)(vs4 + bufo);
#pragma unroll 8
                for (int t = 0; t < TT; t++) {
                    float4 pv = *(const float4*)(sPw + t * 4);   // broadcast
                    ulonglong2 v = vb[t * 32 + lane];
                    u64 p0 = pack2(pv.x);
                    u64 p1 = pack2(pv.y);
                    u64 p2 = pack2(pv.z);
                    u64 p3 = pack2(pv.w);
                    fma2(o[0], p0, v.x); fma2(o[1], p0, v.y);
                    fma2(o[2], p1, v.x); fma2(o[3], p1, v.y);
                    fma2(o[4], p2, v.x); fma2(o[5], p2, v.y);
                    fma2(o[6], p3, v.x); fma2(o[7], p3, v.y);
                }
            }
            __syncthreads();   // C: all warps done with buffers

            if (it + 2 < ntiles) issue_tile(it + 2);
        }
    }

    // ---- store split partials: warp rows R..R+3, lane dims lane*4..+3 ----
    {
#pragma unroll
        for (int rr = 0; rr < 4; rr++) {
            float2 a  = unpack2(o[2 * rr]);
            float2 bf = unpack2(o[2 * rr + 1]);
            *(float4*)(g_po + ((size_t)part * RR + R + rr) * DVV + lane * 4) =
                make_float4(a.x, a.y, bf.x, bf.y);
        }
        if (lane == 0) {
#pragma unroll
            for (int rr = 0; rr < 4; rr++) {
                g_pm[part * RR + R + rr] = m[rr];
                g_pl[part * RR + R + rr] = l[rr];
            }
        }
    }
}

extern "C" __global__ void __launch_bounds__(128)
attn_reduce_kernel(float* __restrict__ out)
{
    __shared__ float4 sV[4][32];
    __shared__ float  sL[4];
    __shared__ float  sM4[4];

    const int hkv = blockIdx.x;
    const int b   = blockIdx.y;
    const int r   = blockIdx.z;          // 0..15
    const int tid = threadIdx.x;
    const int sg  = tid >> 5;            // split group 0..3 (8 splits each)
    const int d4  = tid & 31;
    const int pb  = (b * HKV + hkv) * NSPLIT;

    const float4* po4 = (const float4*)g_po;

    // group max
    float M = -1e30f;
#pragma unroll
    for (int s = 0; s < 8; s++)
        M = fmaxf(M, g_pm[(pb + sg * 8 + s) * RR + r]);
    if (d4 == 0) sM4[sg] = M;
    __syncthreads();
    M = fmaxf(fmaxf(sM4[0], sM4[1]), fmaxf(sM4[2], sM4[3]));

    float lt = 0.f;
    float4 acc = make_float4(0.f, 0.f, 0.f, 0.f);
#pragma unroll
    for (int s = 0; s < 8; s++) {
        const int ss = pb + sg * 8 + s;
        float w = __expf(g_pm[ss * RR + r] - M);
        lt += w * g_pl[ss * RR + r];
        float4 x = po4[((size_t)ss * RR + r) * 32 + d4];
        acc.x += w * x.x; acc.y += w * x.y; acc.z += w * x.z; acc.w += w * x.w;
    }
    sV[sg][d4] = acc;
    if (d4 == 0) sL[sg] = lt;
    __syncthreads();

    if (sg == 0) {
        float4 a0 = sV[0][d4], a1 = sV[1][d4], a2 = sV[2][d4], a3 = sV[3][d4];
        float inv = 1.f / (sL[0] + sL[1] + sL[2] + sL[3]);
        float4 rslt = make_float4((a0.x + a1.x + a2.x + a3.x) * inv,
                                  (a0.y + a1.y + a2.y + a3.y) * inv,
                                  (a0.z + a1.z + a2.z + a3.z) * inv,
                                  (a0.w + a1.w + a2.w + a3.w) * inv);
        const int mq = r & 3;
        const int gi = r >> 2;
        *(float4*)(out + ((size_t)((b * SQ + mq) * HH + hkv * GG + gi)) * DVV + d4 * 4) = rslt;
    }
}

extern "C" void kernel_launch(void* const* d_in, const int* in_sizes, int n_in,
                              void* d_out, int out_size)
{
    const float* Q  = (const float*)d_in[0];
    const float* K  = (const float*)d_in[1];
    const float* V  = (const float*)d_in[2];
    const int*   sl = (const int*)d_in[3];

    cudaFuncSetAttribute(attn_split_kernel,
                         cudaFuncAttributeMaxDynamicSharedMemorySize, SMEM_BYTES);

    attn_split_kernel<<<dim3(NSPLIT, HKV, BB), NTHREADS, SMEM_BYTES>>>(Q, K, V, sl);
    attn_reduce_kernel<<<dim3(HKV, BB, RR), 128>>>((float*)d_out);
}